// round 3
// baseline (speedup 1.0000x reference)
#include <cuda_runtime.h>
#include <cstdint>

#define SEQ  4096
#define DIN  768
#define DOUT 768

// Scratch (allocation-free: __device__ globals).
__device__ float g_Q[SEQ * DOUT];
__device__ float g_K[SEQ * DOUT];
__device__ float g_V[SEQ * DOUT];
__device__ float g_S[(size_t)SEQ * SEQ];

// ---------------------------------------------------------------------------
// helpers
// ---------------------------------------------------------------------------
__device__ __forceinline__ uint32_t f2tf32(float f) {
    uint32_t r;
    asm("cvt.rna.tf32.f32 %0, %1;" : "=r"(r) : "f"(f));
    return r;
}

__device__ __forceinline__ void ldsm4(uint32_t r[4], uint32_t saddr) {
    asm volatile("ldmatrix.sync.aligned.m8n8.x4.shared.b16 {%0,%1,%2,%3}, [%4];"
                 : "=r"(r[0]), "=r"(r[1]), "=r"(r[2]), "=r"(r[3])
                 : "r"(saddr));
}

__device__ __forceinline__ void mma_tf32(float c[4],
                                         const uint32_t a[4],
                                         uint32_t b0, uint32_t b1) {
    asm volatile(
        "mma.sync.aligned.m16n8k8.row.col.f32.tf32.tf32.f32 "
        "{%0,%1,%2,%3}, {%4,%5,%6,%7}, {%8,%9}, {%0,%1,%2,%3};"
        : "+f"(c[0]), "+f"(c[1]), "+f"(c[2]), "+f"(c[3])
        : "r"(a[0]), "r"(a[1]), "r"(a[2]), "r"(a[3]), "r"(b0), "r"(b1));
}

// smem layout: tile [128 rows][16 k-floats] as 16B chunks, XOR swizzled.
// 16B-unit index of (row, chunk c in 0..3):
__device__ __forceinline__ int sw16(int row, int c) {
    return row * 4 + (c ^ ((row >> 1) & 3));
}

// ---------------------------------------------------------------------------
// tf32 tensor-core GEMM: C[M,N] = alpha * A[M,K] @ op(B)
//   TRANS_B=false : B is [K,N] row-major   (C = A @ B)
//   TRANS_B=true  : B is [N,K] row-major   (C = A @ B^T)
// Block 128x128, BK=16, 256 threads (8 warps, 2x4), warp tile 64x32.
// Double-buffered smem (one __syncthreads per K-iter).
// Requires M%128==0, N%128==0, K%16==0.
// ---------------------------------------------------------------------------
template <bool TRANS_B>
__global__ void __launch_bounds__(256, 2)
gemm_tf32(const float* __restrict__ A, const float* __restrict__ B,
          float* __restrict__ C, int M, int N, int K, float alpha)
{
    __shared__ float As[2][128 * 16];
    __shared__ float Bs[2][128 * 16];

    const int tid  = threadIdx.x;
    const int lane = tid & 31;
    const int wid  = tid >> 5;
    const int bm = blockIdx.y * 128;
    const int bn = blockIdx.x * 128;

    const int warp_m = wid & 1;         // 2 warps along M
    const int warp_n = wid >> 1;        // 4 warps along N
    const int m_base = warp_m * 64;
    const int n_base = warp_n * 32;

    // per-lane ldmatrix address components
    const int a_row  = lane & 15;                       // row within 16-row mtile
    const int a_csel = (lane >> 4) & 1;                 // k-chunk select (lo/hi)
    const int b_row  = (lane & 7) + ((lane & 16) >> 1); // row within 16-row npair
    const int b_csel = (lane >> 3) & 1;

    const uint32_t as_base0 = (uint32_t)__cvta_generic_to_shared(&As[0][0]);
    const uint32_t bs_base0 = (uint32_t)__cvta_generic_to_shared(&Bs[0][0]);
    const uint32_t buf_stride = 128 * 16 * 4;  // bytes per buffer

    // gmem->smem loader coords
    const int a_r0 = tid >> 2;
    const int a_c0 = tid & 3;
    const int a_r1 = (tid + 256) >> 2;
    const int a_c1 = tid & 3;
    const int bn_k0 = tid >> 7;        // 0..1
    const int bn_n0 = tid & 127;
    const int bn_k1 = (tid >> 7) + 2;  // 2..3
    const int bn_n1 = tid & 127;

    float acc[4][4][4];
#pragma unroll
    for (int mt = 0; mt < 4; ++mt)
#pragma unroll
        for (int nt = 0; nt < 4; ++nt)
#pragma unroll
            for (int i = 0; i < 4; ++i) acc[mt][nt][i] = 0.0f;

    // prefetch registers
    float4 pa0, pa1;
    float4 pb0, pb1;                 // TRANS_B path
    float  pc0[4], pc1[4];           // non-trans path (gathered columns)

    auto ldg_tile = [&](int k0) {
        pa0 = *reinterpret_cast<const float4*>(&A[(size_t)(bm + a_r0) * K + k0 + a_c0 * 4]);
        pa1 = *reinterpret_cast<const float4*>(&A[(size_t)(bm + a_r1) * K + k0 + a_c1 * 4]);
        if (TRANS_B) {
            pb0 = *reinterpret_cast<const float4*>(&B[(size_t)(bn + a_r0) * K + k0 + a_c0 * 4]);
            pb1 = *reinterpret_cast<const float4*>(&B[(size_t)(bn + a_r1) * K + k0 + a_c1 * 4]);
        } else {
#pragma unroll
            for (int j = 0; j < 4; ++j)
                pc0[j] = B[(size_t)(k0 + bn_k0 * 4 + j) * N + bn + bn_n0];
#pragma unroll
            for (int j = 0; j < 4; ++j)
                pc1[j] = B[(size_t)(k0 + bn_k1 * 4 + j) * N + bn + bn_n1];
        }
    };

    auto sts_tile = [&](int b) {
        float4 t;
        t.x = __uint_as_float(f2tf32(pa0.x)); t.y = __uint_as_float(f2tf32(pa0.y));
        t.z = __uint_as_float(f2tf32(pa0.z)); t.w = __uint_as_float(f2tf32(pa0.w));
        *reinterpret_cast<float4*>(&As[b][sw16(a_r0, a_c0) * 4]) = t;
        t.x = __uint_as_float(f2tf32(pa1.x)); t.y = __uint_as_float(f2tf32(pa1.y));
        t.z = __uint_as_float(f2tf32(pa1.z)); t.w = __uint_as_float(f2tf32(pa1.w));
        *reinterpret_cast<float4*>(&As[b][sw16(a_r1, a_c1) * 4]) = t;
        if (TRANS_B) {
            t.x = __uint_as_float(f2tf32(pb0.x)); t.y = __uint_as_float(f2tf32(pb0.y));
            t.z = __uint_as_float(f2tf32(pb0.z)); t.w = __uint_as_float(f2tf32(pb0.w));
            *reinterpret_cast<float4*>(&Bs[b][sw16(a_r0, a_c0) * 4]) = t;
            t.x = __uint_as_float(f2tf32(pb1.x)); t.y = __uint_as_float(f2tf32(pb1.y));
            t.z = __uint_as_float(f2tf32(pb1.z)); t.w = __uint_as_float(f2tf32(pb1.w));
            *reinterpret_cast<float4*>(&Bs[b][sw16(a_r1, a_c1) * 4]) = t;
        } else {
            t.x = __uint_as_float(f2tf32(pc0[0])); t.y = __uint_as_float(f2tf32(pc0[1]));
            t.z = __uint_as_float(f2tf32(pc0[2])); t.w = __uint_as_float(f2tf32(pc0[3]));
            *reinterpret_cast<float4*>(&Bs[b][sw16(bn_n0, bn_k0) * 4]) = t;
            t.x = __uint_as_float(f2tf32(pc1[0])); t.y = __uint_as_float(f2tf32(pc1[1]));
            t.z = __uint_as_float(f2tf32(pc1[2])); t.w = __uint_as_float(f2tf32(pc1[3]));
            *reinterpret_cast<float4*>(&Bs[b][sw16(bn_n1, bn_k1) * 4]) = t;
        }
    };

    auto compute_tile = [&](int b) {
        const uint32_t as_b = as_base0 + (uint32_t)b * buf_stride;
        const uint32_t bs_b = bs_base0 + (uint32_t)b * buf_stride;
#pragma unroll
        for (int kk = 0; kk < 2; ++kk) {
            uint32_t af[4][4];
#pragma unroll
            for (int mt = 0; mt < 4; ++mt) {
                int m = m_base + mt * 16 + a_row;
                int c = 2 * kk + a_csel;
                ldsm4(af[mt], as_b + sw16(m, c) * 16);
            }
            uint32_t bf[2][4];
#pragma unroll
            for (int np = 0; np < 2; ++np) {
                int n = n_base + np * 16 + b_row;
                int c = 2 * kk + b_csel;
                ldsm4(bf[np], bs_b + sw16(n, c) * 16);
            }
#pragma unroll
            for (int mt = 0; mt < 4; ++mt)
#pragma unroll
                for (int nt = 0; nt < 4; ++nt)
                    mma_tf32(acc[mt][nt], af[mt],
                             bf[nt >> 1][(nt & 1) * 2],
                             bf[nt >> 1][(nt & 1) * 2 + 1]);
        }
    };

    // --- double-buffered main loop: one barrier per K-iteration ---
    ldg_tile(0);
    sts_tile(0);
    __syncthreads();

    const int niter = K / 16;
    int buf = 0;
    for (int it = 1; it < niter; ++it) {
        ldg_tile(it * 16);          // prefetch tile it into registers
        compute_tile(buf);          // compute tile it-1 from buffer `buf`
        sts_tile(buf ^ 1);          // store tile it into the other buffer
        __syncthreads();
        buf ^= 1;
    }
    compute_tile(buf);

    // --- writeback ---
    const int g = lane >> 2;
    const int tq = lane & 3;
#pragma unroll
    for (int mt = 0; mt < 4; ++mt) {
#pragma unroll
        for (int nt = 0; nt < 4; ++nt) {
            const int col = bn + n_base + nt * 8 + tq * 2;
            const int r0 = bm + m_base + mt * 16 + g;
            const int r1 = r0 + 8;
            float2 v0, v1;
            v0.x = alpha * acc[mt][nt][0];
            v0.y = alpha * acc[mt][nt][1];
            v1.x = alpha * acc[mt][nt][2];
            v1.y = alpha * acc[mt][nt][3];
            *reinterpret_cast<float2*>(&C[(size_t)r0 * N + col]) = v0;
            *reinterpret_cast<float2*>(&C[(size_t)r1 * N + col]) = v1;
        }
    }
}

// ---------------------------------------------------------------------------
// Row softmax over S [SEQ, SEQ]. One block per row; row resident in registers.
// ---------------------------------------------------------------------------
__global__ void __launch_bounds__(256)
softmax_kernel(float* __restrict__ S)
{
    const int row = blockIdx.x;
    const int tid = threadIdx.x;
    float* p = S + (size_t)row * SEQ;

    __shared__ float sm_red[8];
    __shared__ float sm_bcast;

    float v[16];
#pragma unroll
    for (int it = 0; it < 4; ++it) {
        float4 t = *reinterpret_cast<const float4*>(&p[it * 1024 + tid * 4]);
        v[it * 4 + 0] = t.x; v[it * 4 + 1] = t.y;
        v[it * 4 + 2] = t.z; v[it * 4 + 3] = t.w;
    }

    float m = v[0];
#pragma unroll
    for (int i = 1; i < 16; ++i) m = fmaxf(m, v[i]);
#pragma unroll
    for (int o = 16; o > 0; o >>= 1) m = fmaxf(m, __shfl_xor_sync(0xffffffffu, m, o));
    if ((tid & 31) == 0) sm_red[tid >> 5] = m;
    __syncthreads();
    if (tid == 0) {
        float mm = sm_red[0];
#pragma unroll
        for (int w = 1; w < 8; ++w) mm = fmaxf(mm, sm_red[w]);
        sm_bcast = mm;
    }
    __syncthreads();
    m = sm_bcast;
    __syncthreads();

    float s = 0.0f;
#pragma unroll
    for (int i = 0; i < 16; ++i) {
        v[i] = __expf(v[i] - m);
        s += v[i];
    }
#pragma unroll
    for (int o = 16; o > 0; o >>= 1) s += __shfl_xor_sync(0xffffffffu, s, o);
    if ((tid & 31) == 0) sm_red[tid >> 5] = s;
    __syncthreads();
    if (tid == 0) {
        float ss = sm_red[0];
#pragma unroll
        for (int w = 1; w < 8; ++w) ss += sm_red[w];
        sm_bcast = ss;
    }
    __syncthreads();
    const float inv = 1.0f / sm_bcast;

#pragma unroll
    for (int it = 0; it < 4; ++it) {
        float4 t;
        t.x = v[it * 4 + 0] * inv; t.y = v[it * 4 + 1] * inv;
        t.z = v[it * 4 + 2] * inv; t.w = v[it * 4 + 3] * inv;
        *reinterpret_cast<float4*>(&p[it * 1024 + tid * 4]) = t;
    }
}

// ---------------------------------------------------------------------------
extern "C" void kernel_launch(void* const* d_in, const int* in_sizes, int n_in,
                              void* d_out, int out_size)
{
    const float* x  = (const float*)d_in[0];
    const float* Wq = (const float*)d_in[1];
    const float* Wk = (const float*)d_in[2];
    const float* Wv = (const float*)d_in[3];
    float* out = (float*)d_out;

    float* Q;  cudaGetSymbolAddress((void**)&Q,  g_Q);
    float* K_; cudaGetSymbolAddress((void**)&K_, g_K);
    float* V;  cudaGetSymbolAddress((void**)&V,  g_V);
    float* S;  cudaGetSymbolAddress((void**)&S,  g_S);

    const float inv_sqrt_d = 0.036084391824351615f;  // 1/sqrt(768)

    dim3 blk(256);
    dim3 grid_qkv(DOUT / 128, SEQ / 128);   // (6, 32)
    dim3 grid_ss(SEQ / 128, SEQ / 128);     // (32, 32)

    // Q, K, V projections
    gemm_tf32<false><<<grid_qkv, blk>>>(x, Wq, Q,  SEQ, DOUT, DIN, 1.0f);
    gemm_tf32<false><<<grid_qkv, blk>>>(x, Wk, K_, SEQ, DOUT, DIN, 1.0f);
    gemm_tf32<false><<<grid_qkv, blk>>>(x, Wv, V,  SEQ, DOUT, DIN, 1.0f);

    // scores = (Q @ K^T) / sqrt(d)
    gemm_tf32<true><<<grid_ss, blk>>>(Q, K_, S, SEQ, SEQ, DOUT, inv_sqrt_d);

    // row softmax
    softmax_kernel<<<SEQ, blk>>>(S);

    // out = weights @ V
    gemm_tf32<false><<<grid_qkv, blk>>>(S, V, out, SEQ, DOUT, SEQ, 1.0f);
}